// round 3
// baseline (speedup 1.0000x reference)
#include <cuda_runtime.h>
#include <cstdint>
#include <cstddef>

#define NN   50000
#define EE   800000
#define INC  512
#define OUTC 256
#define DECD 256

// Scratch (device globals — no allocation allowed)
__device__ float g_deg[NN];
__device__ float g_dinv[NN];
__device__ int   g_flag[NN];
__device__ float g_bufA[(size_t)NN * OUTC];
__device__ float g_bufB[(size_t)NN * OUTC];
__device__ float g_bufC[(size_t)NN * OUTC];

// ---------------------------------------------------------------- small ops
__global__ void k_zero() {
    int i = blockIdx.x * blockDim.x + threadIdx.x;
    if (i < NN) { g_deg[i] = 0.0f; g_flag[i] = 0; }
}

__global__ void k_deg(const int* __restrict__ dst) {
    int e = blockIdx.x * blockDim.x + threadIdx.x;
    if (e < EE) atomicAdd(&g_deg[dst[e]], 1.0f);
}

__global__ void k_flag(const int* __restrict__ midx, int nm) {
    int i = blockIdx.x * blockDim.x + threadIdx.x;
    if (i < nm) g_flag[midx[i]] = 1;
}

__global__ void k_dinv() {
    int i = blockIdx.x * blockDim.x + threadIdx.x;
    if (i < NN) g_dinv[i] = rsqrtf(g_deg[i] + 1.0f);
}

// mask_indices tail of output: convert int32 -> float32
__global__ void k_midx_out(const int* __restrict__ midx, float* __restrict__ out, int nm) {
    int i = blockIdx.x * blockDim.x + threadIdx.x;
    if (i < nm) out[i] = (float)midx[i];
}

// copy x into output slot 1
__global__ void k_copy_x(const float* __restrict__ x, float* __restrict__ out) {
    size_t idx = (size_t)blockIdx.x * blockDim.x + threadIdx.x;   // float4 index
    if (idx < (size_t)NN * (INC / 4))
        *(float4*)(out + idx * 4) = *(const float4*)(x + idx * 4);
}

// agg = h * dinv^2 + bias   (self-loop term, also replaces zero-init)
__global__ void k_init(const float* __restrict__ h, const float* __restrict__ b,
                       float* __restrict__ agg) {
    size_t idx = (size_t)blockIdx.x * blockDim.x + threadIdx.x;   // float4 index
    if (idx >= (size_t)NN * (OUTC / 4)) return;
    int i  = (int)(idx >> 6);
    int j4 = (int)(idx & 63) << 2;
    float di = g_dinv[i];
    float s = di * di;
    float4 hv = *(const float4*)(h + idx * 4);
    float4 bv = *(const float4*)(b + j4);
    float4 o;
    o.x = hv.x * s + bv.x;  o.y = hv.y * s + bv.y;
    o.z = hv.z * s + bv.z;  o.w = hv.w * s + bv.w;
    *(float4*)(agg + idx * 4) = o;
}

// agg[dst] += h[src] * dinv[src]*dinv[dst]  — 64 threads per edge, float4 + red.v4
__global__ void k_scatter(const float* __restrict__ h, const int* __restrict__ src,
                          const int* __restrict__ dst, float* __restrict__ agg) {
    long long gid = (long long)blockIdx.x * blockDim.x + threadIdx.x;
    int e    = (int)(gid >> 6);
    int lane = (int)(gid & 63);
    if (e >= EE) return;
    int s = src[e], d = dst[e];
    float c = g_dinv[s] * g_dinv[d];
    float4 v = *(const float4*)(h + (size_t)s * OUTC + lane * 4);
    float* ap = agg + (size_t)d * OUTC + lane * 4;
    asm volatile("red.global.add.v4.f32 [%0], {%1, %2, %3, %4};"
                 :: "l"(ap), "f"(v.x * c), "f"(v.y * c), "f"(v.z * c), "f"(v.w * c)
                 : "memory");
}

// ---------------------------------------------------------------- SGEMM
// C[M,N] = op(A[M,K]) @ B[K,N] (+ bias).  128x128x8 tile, 256 threads, 8x8/thread.
// MASK: rows with g_flag==1 read mask_token instead of A-row (GEMM1).
// RELU: relu applied to A elements at load (GEMM3).
template<bool MASK, bool RELU, bool BIAS>
__global__ void __launch_bounds__(256)
k_sgemm(const float* __restrict__ A, const float* __restrict__ B, float* __restrict__ C,
        int M, int N, int K, const float* __restrict__ bias, const float* __restrict__ mtok) {
    __shared__ float As[8][128];
    __shared__ float Bs[8][128];

    const int tid  = threadIdx.x;
    const int rowA = tid >> 1;            // 0..127
    const int kA   = (tid & 1) << 2;      // 0 or 4
    const int rowB = tid >> 5;            // 0..7
    const int colB = (tid & 31) << 2;     // 0..124

    const int  gr    = blockIdx.y * 128 + rowA;
    const bool valid = gr < M;
    const int  grs   = valid ? gr : 0;

    const float* aptr;
    if (MASK && valid && g_flag[grs]) aptr = mtok + kA;
    else                              aptr = A + (size_t)grs * K + kA;
    const float* bptr = B + (size_t)rowB * N + blockIdx.x * 128 + colB;

    const int tx = tid & 15, ty = tid >> 4;

    float acc[8][8];
#pragma unroll
    for (int i = 0; i < 8; i++)
#pragma unroll
        for (int j = 0; j < 8; j++) acc[i][j] = 0.0f;

    for (int kt = 0; kt < K; kt += 8) {
        float4 av = make_float4(0.f, 0.f, 0.f, 0.f);
        if (valid) av = *(const float4*)aptr;
        if (RELU) {
            av.x = fmaxf(av.x, 0.f); av.y = fmaxf(av.y, 0.f);
            av.z = fmaxf(av.z, 0.f); av.w = fmaxf(av.w, 0.f);
        }
        float4 bv = *(const float4*)bptr;

        __syncthreads();
        As[kA + 0][rowA] = av.x;
        As[kA + 1][rowA] = av.y;
        As[kA + 2][rowA] = av.z;
        As[kA + 3][rowA] = av.w;
        *(float4*)&Bs[rowB][colB] = bv;
        __syncthreads();

#pragma unroll
        for (int k = 0; k < 8; k++) {
            float ar[8], br[8];
            *(float4*)&ar[0] = *(const float4*)&As[k][ty * 8];
            *(float4*)&ar[4] = *(const float4*)&As[k][ty * 8 + 4];
            *(float4*)&br[0] = *(const float4*)&Bs[k][tx * 8];
            *(float4*)&br[4] = *(const float4*)&Bs[k][tx * 8 + 4];
#pragma unroll
            for (int i = 0; i < 8; i++)
#pragma unroll
                for (int j = 0; j < 8; j++)
                    acc[i][j] = fmaf(ar[i], br[j], acc[i][j]);
        }
        aptr += 8;
        bptr += (size_t)8 * N;
    }

    const int crow0 = blockIdx.y * 128 + ty * 8;
    const int ccol0 = blockIdx.x * 128 + tx * 8;
#pragma unroll
    for (int i = 0; i < 8; i++) {
        int r = crow0 + i;
        if (r < M) {
#pragma unroll
            for (int j = 0; j < 8; j += 4) {
                float4 v;
                v.x = acc[i][j + 0] + (BIAS ? bias[ccol0 + j + 0] : 0.f);
                v.y = acc[i][j + 1] + (BIAS ? bias[ccol0 + j + 1] : 0.f);
                v.z = acc[i][j + 2] + (BIAS ? bias[ccol0 + j + 2] : 0.f);
                v.w = acc[i][j + 3] + (BIAS ? bias[ccol0 + j + 3] : 0.f);
                *(float4*)(C + (size_t)r * N + ccol0 + j) = v;
            }
        }
    }
}

// ---------------------------------------------------------------- launch
extern "C" void kernel_launch(void* const* d_in, const int* in_sizes, int n_in,
                              void* d_out, int out_size) {
    const float* x    = (const float*)d_in[0];
    const int*   eidx = (const int*)d_in[1];
    const int*   midx = (const int*)d_in[2];
    const float* mtok = (const float*)d_in[3];
    const float* encW = (const float*)d_in[4];
    const float* encb = (const float*)d_in[5];
    const float* decW = (const float*)d_in[6];
    const float* decb = (const float*)d_in[7];
    const float* mlpW = (const float*)d_in[8];
    const float* mlpb = (const float*)d_in[9];

    const int nm = in_sizes[2];
    const int* src = eidx;
    const int* dst = eidx + EE;

    float *bufA, *bufB, *bufC;
    cudaGetSymbolAddress((void**)&bufA, g_bufA);
    cudaGetSymbolAddress((void**)&bufB, g_bufB);
    cudaGetSymbolAddress((void**)&bufC, g_bufC);

    float* out = (float*)d_out;

    // norm + mask flags
    k_zero<<<(NN + 255) / 256, 256>>>();
    k_deg<<<(EE + 255) / 256, 256>>>(dst);
    k_flag<<<(nm + 255) / 256, 256>>>(midx, nm);
    k_dinv<<<(NN + 255) / 256, 256>>>();

    dim3 g1(OUTC / 128, (NN + 127) / 128);
    dim3 g3(INC / 128, (NN + 127) / 128);
    const int initBlocks = (int)(((size_t)NN * (OUTC / 4) + 255) / 256);
    const int scatBlocks = (int)(((long long)EE * 64 + 255) / 256);

    // encoder: h1 = x_masked @ encW ; z = agg(h1) + h1*dinv^2 + encb
    k_sgemm<true, false, false><<<g1, 256>>>(x, encW, bufA, NN, OUTC, INC, nullptr, mtok);
    k_init<<<initBlocks, 256>>>(bufA, encb, bufB);
    k_scatter<<<scatBlocks, 256>>>(bufA, src, dst, bufB);

    // decoder conv: h2pre = z @ decW ; pre-relu h2 = agg(h2pre) + h2pre*dinv^2 + decb
    k_sgemm<false, false, false><<<g1, 256>>>(bufB, decW, bufA, NN, DECD, OUTC, nullptr, nullptr);
    k_init<<<initBlocks, 256>>>(bufA, decb, bufC);
    k_scatter<<<scatBlocks, 256>>>(bufA, src, dst, bufC);

    // mlp: x_recon = relu(h2) @ mlpW + mlpb   (relu fused into A-load)
    k_sgemm<false, true, true><<<g3, 256>>>(bufC, mlpW, out, NN, INC, DECD, mlpb, nullptr);

    // output tail: x (slot 1, float copy), mask_indices (slot 2, int->float convert)
    const size_t reconElems = (size_t)NN * INC;
    k_copy_x<<<(int)((reconElems / 4 + 255) / 256), 256>>>(x, out + reconElems);
    k_midx_out<<<(nm + 255) / 256, 256>>>(midx, out + 2 * reconElems, nm);
}

// round 6
// speedup vs baseline: 1.4349x; 1.4349x over previous
#include <cuda_runtime.h>
#include <cstdint>
#include <cstddef>

#define NN   50000
#define EE   800000
#define INC  512
#define OUTC 256
#define DECD 256
#define NBLK 391        // ceil(NN/128)

// Scratch (device globals — no allocation allowed)
__device__ float g_deg[NN];
__device__ float g_dinv[NN];
__device__ int   g_flag[NN];
__device__ float g_bufA[(size_t)NN * OUTC];
__device__ float g_bufB[(size_t)NN * OUTC];
__device__ float g_bufC[(size_t)NN * OUTC];

// ---------------------------------------------------------------- small ops
__global__ void k_zero() {
    int i = blockIdx.x * blockDim.x + threadIdx.x;
    if (i < NN) { g_deg[i] = 0.0f; g_flag[i] = 0; }
}
__global__ void k_deg(const int* __restrict__ dst) {
    int e = blockIdx.x * blockDim.x + threadIdx.x;
    if (e < EE) atomicAdd(&g_deg[dst[e]], 1.0f);
}
__global__ void k_flag(const int* __restrict__ midx, int nm) {
    int i = blockIdx.x * blockDim.x + threadIdx.x;
    if (i < nm) g_flag[midx[i]] = 1;
}
__global__ void k_dinv() {
    int i = blockIdx.x * blockDim.x + threadIdx.x;
    if (i < NN) g_dinv[i] = rsqrtf(g_deg[i] + 1.0f);
}
__global__ void k_midx_out(const int* __restrict__ midx, float* __restrict__ out, int nm) {
    int i = blockIdx.x * blockDim.x + threadIdx.x;
    if (i < nm) out[i] = (float)midx[i];
}
__global__ void k_copy_x(const float* __restrict__ x, float* __restrict__ out) {
    size_t idx = (size_t)blockIdx.x * blockDim.x + threadIdx.x;
    if (idx < (size_t)NN * (INC / 4))
        *(float4*)(out + idx * 4) = *(const float4*)(x + idx * 4);
}

// agg[dst] += h[src] * dinv[src]*dinv[dst]  — 64 threads per edge, float4 + red.v4
__global__ void k_scatter(const float* __restrict__ h, const int* __restrict__ src,
                          const int* __restrict__ dst, float* __restrict__ agg) {
    long long gid = (long long)blockIdx.x * blockDim.x + threadIdx.x;
    int e    = (int)(gid >> 6);
    int lane = (int)(gid & 63);
    if (e >= EE) return;
    int s = src[e], d = dst[e];
    float c = g_dinv[s] * g_dinv[d];
    float4 v = *(const float4*)(h + (size_t)s * OUTC + lane * 4);
    float* ap = agg + (size_t)d * OUTC + lane * 4;
    asm volatile("red.global.add.v4.f32 [%0], {%1, %2, %3, %4};"
                 :: "l"(ap), "f"(v.x * c), "f"(v.y * c), "f"(v.z * c), "f"(v.w * c)
                 : "memory");
}

// ---------------------------------------------------------------- tf32 mma.sync GEMM
__device__ __forceinline__ uint32_t f2tf32(float f) {
    uint32_t u;
    asm("cvt.rna.tf32.f32 %0, %1;" : "=r"(u) : "f"(f));
    return u;
}
__device__ __forceinline__ void cvt4(float4& v) {
    ((uint32_t*)&v)[0] = f2tf32(v.x);
    ((uint32_t*)&v)[1] = f2tf32(v.y);
    ((uint32_t*)&v)[2] = f2tf32(v.z);
    ((uint32_t*)&v)[3] = f2tf32(v.w);
}
__device__ __forceinline__ void mma8(float* c, const uint32_t* a, const uint32_t* b) {
    asm volatile(
        "mma.sync.aligned.m16n8k8.row.col.f32.tf32.tf32.f32 "
        "{%0,%1,%2,%3}, {%4,%5,%6,%7}, {%8,%9}, {%0,%1,%2,%3};"
        : "+f"(c[0]), "+f"(c[1]), "+f"(c[2]), "+f"(c[3])
        : "r"(a[0]), "r"(a[1]), "r"(a[2]), "r"(a[3]), "r"(b[0]), "r"(b[1]));
}

// C[128-tile, 128-tile] = op(A[M,K_TOT]) @ W[K_TOT,N_TOT] (+ bias)
// MASK: mask_token row substitution (GEMM1); RELU: relu at A load (GEMM3)
// DUAL: outH = C, outZ = C*dinv^2 + bias ; !DUAL: outH = C + bias
template<int N_TOT, int K_TOT, bool MASK, bool RELU, bool DUAL>
__global__ void __launch_bounds__(256, 1)
k_mma(const float* __restrict__ A, const float* __restrict__ W,
      float* __restrict__ outH, float* __restrict__ outZ,
      const float* __restrict__ bias, const float* __restrict__ mtok)
{
    constexpr int NC   = K_TOT / 32;        // K chunks
    constexpr int ASTR = 36;                // A smem row stride (floats)
    constexpr int BSTR = 132;               // B smem row stride (floats)
    constexpr int ASZ  = 128 * ASTR;        // 4608 floats
    constexpr int BSZ  = 32 * BSTR;         // 4224 floats

    extern __shared__ float sm[];
    float* Abuf = sm;                       // 2 * ASZ
    float* Bbuf = sm + 2 * ASZ;             // 2 * BSZ

    const int tid   = threadIdx.x;
    const int wid   = tid >> 5;
    const int lane  = tid & 31;
    const int g     = lane >> 2;            // group id 0..7
    const int tig   = lane & 3;             // thread in group
    const int warpM = wid >> 2;             // 0..1 -> 64 rows
    const int warpN = wid & 3;              // 0..3 -> 32 cols
    const int m0    = blockIdx.y * 128;
    const int n0    = blockIdx.x * 128;

    float acc[4][4][4];
#pragma unroll
    for (int mt = 0; mt < 4; mt++)
#pragma unroll
        for (int nt = 0; nt < 4; nt++)
#pragma unroll
            for (int i = 0; i < 4; i++) acc[mt][nt][i] = 0.0f;

    // per-thread global load slots
    float4 rA[4], rB[4];

    auto ldg = [&](int c) {
        const int k0 = c * 32;
#pragma unroll
        for (int t = 0; t < 4; t++) {
            int idx = tid + t * 256;
            int r = idx >> 3, q = idx & 7;
            int gr = m0 + r;
            float4 v = make_float4(0.f, 0.f, 0.f, 0.f);
            if (gr < NN) {
                const float* p;
                if (MASK && g_flag[gr]) p = mtok + k0 + q * 4;
                else                    p = A + (size_t)gr * K_TOT + k0 + q * 4;
                v = *(const float4*)p;
                if (RELU) {
                    v.x = fmaxf(v.x, 0.f); v.y = fmaxf(v.y, 0.f);
                    v.z = fmaxf(v.z, 0.f); v.w = fmaxf(v.w, 0.f);
                }
            }
            cvt4(v);
            rA[t] = v;
        }
#pragma unroll
        for (int t = 0; t < 4; t++) {
            int idx = tid + t * 256;
            int kk = idx >> 5, n4 = idx & 31;
            float4 v = *(const float4*)(W + (size_t)(k0 + kk) * N_TOT + n0 + n4 * 4);
            cvt4(v);
            rB[t] = v;
        }
    };
    auto sts = [&](int b) {
        float* As = Abuf + b * ASZ;
        float* Bs = Bbuf + b * BSZ;
#pragma unroll
        for (int t = 0; t < 4; t++) {
            int idx = tid + t * 256;
            int r = idx >> 3, q = idx & 7;
            *(float4*)(As + r * ASTR + q * 4) = rA[t];
        }
#pragma unroll
        for (int t = 0; t < 4; t++) {
            int idx = tid + t * 256;
            int kk = idx >> 5, n4 = idx & 31;
            *(float4*)(Bs + kk * BSTR + n4 * 4) = rB[t];
        }
    };

    // prologue
    ldg(0);
    sts(0);
    __syncthreads();

    for (int c = 0; c < NC; c++) {
        const int b = c & 1;
        if (c + 1 < NC) ldg(c + 1);      // overlap with compute below

        const float* As = Abuf + b * ASZ;
        const float* Bs = Bbuf + b * BSZ;
#pragma unroll
        for (int kt = 0; kt < 4; kt++) {
            uint32_t af[4][4], bf[4][2];
            const float* ab = As + (warpM * 64 + g) * ASTR + kt * 8 + tig;
#pragma unroll
            for (int mt = 0; mt < 4; mt++) {
                const float* p = ab + mt * 16 * ASTR;
                af[mt][0] = __float_as_uint(p[0]);
                af[mt][1] = __float_as_uint(p[8 * ASTR]);
                af[mt][2] = __float_as_uint(p[4]);
                af[mt][3] = __float_as_uint(p[8 * ASTR + 4]);
            }
            const float* bb = Bs + (kt * 8 + tig) * BSTR + warpN * 32 + g;
#pragma unroll
            for (int nt = 0; nt < 4; nt++) {
                const float* p = bb + nt * 8;
                bf[nt][0] = __float_as_uint(p[0]);
                bf[nt][1] = __float_as_uint(p[4 * BSTR]);
            }
#pragma unroll
            for (int mt = 0; mt < 4; mt++)
#pragma unroll
                for (int nt = 0; nt < 4; nt++)
                    mma8(acc[mt][nt], af[mt], bf[nt]);
        }
        __syncthreads();
        if (c + 1 < NC) {
            sts((c + 1) & 1);
            __syncthreads();
        }
    }

    // epilogue
#pragma unroll
    for (int mt = 0; mt < 4; mt++) {
        const int row0 = m0 + warpM * 64 + mt * 16 + g;
        const int row1 = row0 + 8;
        float s0 = 0.f, s1 = 0.f;
        if (DUAL) {
            if (row0 < NN) { float d = g_dinv[row0]; s0 = d * d; }
            if (row1 < NN) { float d = g_dinv[row1]; s1 = d * d; }
        }
#pragma unroll
        for (int nt = 0; nt < 4; nt++) {
            const int col = n0 + warpN * 32 + nt * 8 + 2 * tig;
            const float2 bz = *(const float2*)(bias + col);
            const float* cc = acc[mt][nt];
            if (row0 < NN) {
                size_t o = (size_t)row0 * N_TOT + col;
                if (DUAL) {
                    *(float2*)(outH + o) = make_float2(cc[0], cc[1]);
                    *(float2*)(outZ + o) = make_float2(cc[0] * s0 + bz.x, cc[1] * s0 + bz.y);
                } else {
                    *(float2*)(outH + o) = make_float2(cc[0] + bz.x, cc[1] + bz.y);
                }
            }
            if (row1 < NN) {
                size_t o = (size_t)row1 * N_TOT + col;
                if (DUAL) {
                    *(float2*)(outH + o) = make_float2(cc[2], cc[3]);
                    *(float2*)(outZ + o) = make_float2(cc[2] * s1 + bz.x, cc[3] * s1 + bz.y);
                } else {
                    *(float2*)(outH + o) = make_float2(cc[2] + bz.x, cc[3] + bz.y);
                }
            }
        }
    }
}

// ---------------------------------------------------------------- launch
extern "C" void kernel_launch(void* const* d_in, const int* in_sizes, int n_in,
                              void* d_out, int out_size) {
    const float* x    = (const float*)d_in[0];
    const int*   eidx = (const int*)d_in[1];
    const int*   midx = (const int*)d_in[2];
    const float* mtok = (const float*)d_in[3];
    const float* encW = (const float*)d_in[4];
    const float* encb = (const float*)d_in[5];
    const float* decW = (const float*)d_in[6];
    const float* decb = (const float*)d_in[7];
    const float* mlpW = (const float*)d_in[8];
    const float* mlpb = (const float*)d_in[9];

    const int nm = in_sizes[2];
    const int* src = eidx;
    const int* dst = eidx + EE;

    float *bufA, *bufB, *bufC;
    cudaGetSymbolAddress((void**)&bufA, g_bufA);
    cudaGetSymbolAddress((void**)&bufB, g_bufB);
    cudaGetSymbolAddress((void**)&bufC, g_bufC);
    float* out = (float*)d_out;

    const int SMEM = (2 * 128 * 36 + 2 * 32 * 132) * 4;   // 70656 B
    cudaFuncSetAttribute(k_mma<OUTC, INC,  true,  false, true>,
                         cudaFuncAttributeMaxDynamicSharedMemorySize, SMEM);
    cudaFuncSetAttribute(k_mma<OUTC, OUTC, false, false, true>,
                         cudaFuncAttributeMaxDynamicSharedMemorySize, SMEM);
    cudaFuncSetAttribute(k_mma<INC,  DECD, false, true,  false>,
                         cudaFuncAttributeMaxDynamicSharedMemorySize, SMEM);

    // norm + mask flags
    k_zero<<<(NN + 255) / 256, 256>>>();
    k_deg<<<(EE + 255) / 256, 256>>>(dst);
    k_flag<<<(nm + 255) / 256, 256>>>(midx, nm);
    k_dinv<<<(NN + 255) / 256, 256>>>();

    const int scatBlocks = (int)(((long long)EE * 64 + 255) / 256);

    // encoder: h1 = x_masked @ encW ; bufB = h1*dinv^2 + encb ; scatter adds edges
    k_mma<OUTC, INC, true, false, true><<<dim3(OUTC / 128, NBLK), 256, SMEM>>>(
        x, encW, bufA, bufB, encb, mtok);
    k_scatter<<<scatBlocks, 256>>>(bufA, src, dst, bufB);

    // decoder conv: h2pre = z @ decW ; bufC = h2pre*dinv^2 + decb ; scatter adds edges
    k_mma<OUTC, OUTC, false, false, true><<<dim3(OUTC / 128, NBLK), 256, SMEM>>>(
        bufB, decW, bufA, bufC, decb, nullptr);
    k_scatter<<<scatBlocks, 256>>>(bufA, src, dst, bufC);

    // mlp: x_recon = relu(h2) @ mlpW + mlpb
    k_mma<INC, DECD, false, true, false><<<dim3(INC / 128, NBLK), 256, SMEM>>>(
        bufC, mlpW, out, nullptr, mlpb, nullptr);

    // output tail: x (slot 1), mask_indices as float (slot 2)
    const size_t reconElems = (size_t)NN * INC;
    k_copy_x<<<(int)((reconElems / 4 + 255) / 256), 256>>>(x, out + reconElems);
    k_midx_out<<<(nm + 255) / 256, 256>>>(midx, out + 2 * reconElems, nm);
}

// round 7
// speedup vs baseline: 2.1166x; 1.4750x over previous
#include <cuda_runtime.h>
#include <cstdint>
#include <cstddef>

#define NN   50000
#define EE   800000
#define INC  512
#define OUTC 256
#define DECD 256
#define NBLK 391        // ceil(NN/128)
#define SBLK 196        // ceil(NN/256)

// Scratch (device globals — no allocation allowed)
__device__ float g_dinv[NN];
__device__ int   g_flag[NN];
__device__ int   g_cnt[NN];
__device__ int   g_rowptr[NN + 1];
__device__ int   g_bsum[256];
__device__ int   g_cur[NN];
__device__ int   g_esrc[EE];
__device__ float g_bufA[(size_t)NN * OUTC];
__device__ float g_bufB[(size_t)NN * OUTC];
__device__ float g_bufC[(size_t)NN * OUTC];

// ---------------------------------------------------------------- CSR build
__global__ void k_zero() {
    int i = blockIdx.x * blockDim.x + threadIdx.x;
    if (i < NN) { g_cnt[i] = 0; g_flag[i] = 0; }
}
__global__ void k_deg(const int* __restrict__ dst) {
    int e = blockIdx.x * blockDim.x + threadIdx.x;
    if (e < EE) atomicAdd(&g_cnt[dst[e]], 1);
}
__global__ void k_scan1() {
    __shared__ int s[256];
    int gid = blockIdx.x * 256 + threadIdx.x;
    int v = (gid < NN) ? g_cnt[gid] : 0;
    s[threadIdx.x] = v;
    __syncthreads();
#pragma unroll
    for (int off = 1; off < 256; off <<= 1) {
        int t = (threadIdx.x >= off) ? s[threadIdx.x - off] : 0;
        __syncthreads();
        s[threadIdx.x] += t;
        __syncthreads();
    }
    if (gid < NN) g_rowptr[gid] = s[threadIdx.x] - v;     // block-local exclusive
    if (threadIdx.x == 255) g_bsum[blockIdx.x] = s[255];
}
__global__ void k_scan2() {
    __shared__ int s[256];
    int v = (threadIdx.x < SBLK) ? g_bsum[threadIdx.x] : 0;
    s[threadIdx.x] = v;
    __syncthreads();
#pragma unroll
    for (int off = 1; off < 256; off <<= 1) {
        int t = (threadIdx.x >= off) ? s[threadIdx.x - off] : 0;
        __syncthreads();
        s[threadIdx.x] += t;
        __syncthreads();
    }
    if (threadIdx.x < SBLK) g_bsum[threadIdx.x] = s[threadIdx.x] - v;  // exclusive
    if (threadIdx.x == 0) g_rowptr[NN] = EE;
}
__global__ void k_scan3() {
    int gid = blockIdx.x * 256 + threadIdx.x;
    if (gid < NN) {
        int r = g_rowptr[gid] + g_bsum[blockIdx.x];
        g_rowptr[gid] = r;
        g_cur[gid] = r;
    }
}
__global__ void k_dinv() {
    int i = blockIdx.x * blockDim.x + threadIdx.x;
    if (i < NN) {
        float deg = (float)(g_rowptr[i + 1] - g_rowptr[i]);
        g_dinv[i] = rsqrtf(deg + 1.0f);
    }
}
__global__ void k_fill(const int* __restrict__ src, const int* __restrict__ dst) {
    int e = blockIdx.x * blockDim.x + threadIdx.x;
    if (e < EE) {
        int p = atomicAdd(&g_cur[dst[e]], 1);
        g_esrc[p] = src[e];
    }
}
__global__ void k_flag(const int* __restrict__ midx, int nm) {
    int i = blockIdx.x * blockDim.x + threadIdx.x;
    if (i < nm) g_flag[midx[i]] = 1;
}

// ---------------------------------------------------------------- output tail
__global__ void k_midx_out(const int* __restrict__ midx, float* __restrict__ out, int nm) {
    int i = blockIdx.x * blockDim.x + threadIdx.x;
    if (i < nm) out[i] = (float)midx[i];
}
__global__ void k_copy_x(const float* __restrict__ x, float* __restrict__ out) {
    size_t idx = (size_t)blockIdx.x * blockDim.x + threadIdx.x;
    if (idx < (size_t)NN * (INC / 4))
        *(float4*)(out + idx * 4) = *(const float4*)(x + idx * 4);
}

// ---------------------------------------------------------------- pull-mode aggregation
// z[node] = sum_{e: dst=node} h[src_e]*dinv[src_e]*dinv[node] + h[node]*dinv^2 + bias
// 64 threads per node (float4 over 256 channels), 4 nodes per 256-thread block.
__global__ void __launch_bounds__(256)
k_gather(const float* __restrict__ h, const float* __restrict__ bias,
         float* __restrict__ z) {
    const int node = blockIdx.x * 4 + (threadIdx.x >> 6);
    const int lane = threadIdx.x & 63;
    if (node >= NN) return;
    const int beg = g_rowptr[node];
    const int end = g_rowptr[node + 1];
    const float dn = g_dinv[node];

    const float4 bz = *(const float4*)(bias + lane * 4);
    float4 hv = *(const float4*)(h + (size_t)node * OUTC + lane * 4);
    const float s = dn * dn;
    float4 acc;
    acc.x = hv.x * s + bz.x;  acc.y = hv.y * s + bz.y;
    acc.z = hv.z * s + bz.z;  acc.w = hv.w * s + bz.w;

    int sidx = (beg < end) ? __ldg(&g_esrc[beg]) : 0;
    for (int i = beg; i < end; i++) {
        int nsidx = (i + 1 < end) ? __ldg(&g_esrc[i + 1]) : 0;
        float c = g_dinv[sidx] * dn;
        float4 v = *(const float4*)(h + (size_t)sidx * OUTC + lane * 4);
        acc.x += v.x * c;  acc.y += v.y * c;
        acc.z += v.z * c;  acc.w += v.w * c;
        sidx = nsidx;
    }
    *(float4*)(z + (size_t)node * OUTC + lane * 4) = acc;
}

// ---------------------------------------------------------------- tf32 mma.sync GEMM
__device__ __forceinline__ uint32_t f2tf32(float f) {
    uint32_t u;
    asm("cvt.rna.tf32.f32 %0, %1;" : "=r"(u) : "f"(f));
    return u;
}
__device__ __forceinline__ void cvt4(float4& v) {
    ((uint32_t*)&v)[0] = f2tf32(v.x);
    ((uint32_t*)&v)[1] = f2tf32(v.y);
    ((uint32_t*)&v)[2] = f2tf32(v.z);
    ((uint32_t*)&v)[3] = f2tf32(v.w);
}
__device__ __forceinline__ void mma8(float* c, const uint32_t* a, const uint32_t* b) {
    asm volatile(
        "mma.sync.aligned.m16n8k8.row.col.f32.tf32.tf32.f32 "
        "{%0,%1,%2,%3}, {%4,%5,%6,%7}, {%8,%9}, {%0,%1,%2,%3};"
        : "+f"(c[0]), "+f"(c[1]), "+f"(c[2]), "+f"(c[3])
        : "r"(a[0]), "r"(a[1]), "r"(a[2]), "r"(a[3]), "r"(b[0]), "r"(b[1]));
}

// C[128-tile, 128-tile] = op(A[M,K_TOT]) @ W[K_TOT,N_TOT] (+ bias if BIAS)
// MASK: mask_token row substitution; RELU: relu at A load
template<int N_TOT, int K_TOT, bool MASK, bool RELU, bool BIAS>
__global__ void __launch_bounds__(256, 1)
k_mma(const float* __restrict__ A, const float* __restrict__ W,
      float* __restrict__ outH, const float* __restrict__ bias,
      const float* __restrict__ mtok)
{
    constexpr int NC   = K_TOT / 32;
    constexpr int ASTR = 36;
    constexpr int BSTR = 132;
    constexpr int ASZ  = 128 * ASTR;
    constexpr int BSZ  = 32 * BSTR;

    extern __shared__ float sm[];
    float* Abuf = sm;
    float* Bbuf = sm + 2 * ASZ;

    const int tid   = threadIdx.x;
    const int wid   = tid >> 5;
    const int lane  = tid & 31;
    const int g     = lane >> 2;
    const int tig   = lane & 3;
    const int warpM = wid >> 2;
    const int warpN = wid & 3;
    const int m0    = blockIdx.y * 128;
    const int n0    = blockIdx.x * 128;

    float acc[4][4][4];
#pragma unroll
    for (int mt = 0; mt < 4; mt++)
#pragma unroll
        for (int nt = 0; nt < 4; nt++)
#pragma unroll
            for (int i = 0; i < 4; i++) acc[mt][nt][i] = 0.0f;

    float4 rA[4], rB[4];

    auto ldg = [&](int c) {
        const int k0 = c * 32;
#pragma unroll
        for (int t = 0; t < 4; t++) {
            int idx = tid + t * 256;
            int r = idx >> 3, q = idx & 7;
            int gr = m0 + r;
            float4 v = make_float4(0.f, 0.f, 0.f, 0.f);
            if (gr < NN) {
                const float* p;
                if (MASK && g_flag[gr]) p = mtok + k0 + q * 4;
                else                    p = A + (size_t)gr * K_TOT + k0 + q * 4;
                v = *(const float4*)p;
                if (RELU) {
                    v.x = fmaxf(v.x, 0.f); v.y = fmaxf(v.y, 0.f);
                    v.z = fmaxf(v.z, 0.f); v.w = fmaxf(v.w, 0.f);
                }
            }
            cvt4(v);
            rA[t] = v;
        }
#pragma unroll
        for (int t = 0; t < 4; t++) {
            int idx = tid + t * 256;
            int kk = idx >> 5, n4 = idx & 31;
            float4 v = *(const float4*)(W + (size_t)(k0 + kk) * N_TOT + n0 + n4 * 4);
            cvt4(v);
            rB[t] = v;
        }
    };
    auto sts = [&](int b) {
        float* As = Abuf + b * ASZ;
        float* Bs = Bbuf + b * BSZ;
#pragma unroll
        for (int t = 0; t < 4; t++) {
            int idx = tid + t * 256;
            int r = idx >> 3, q = idx & 7;
            *(float4*)(As + r * ASTR + q * 4) = rA[t];
        }
#pragma unroll
        for (int t = 0; t < 4; t++) {
            int idx = tid + t * 256;
            int kk = idx >> 5, n4 = idx & 31;
            *(float4*)(Bs + kk * BSTR + n4 * 4) = rB[t];
        }
    };

    ldg(0);
    sts(0);
    __syncthreads();

    for (int c = 0; c < NC; c++) {
        const int b = c & 1;
        if (c + 1 < NC) ldg(c + 1);

        const float* As = Abuf + b * ASZ;
        const float* Bs = Bbuf + b * BSZ;
#pragma unroll
        for (int kt = 0; kt < 4; kt++) {
            uint32_t af[4][4], bf[4][2];
            const float* ab = As + (warpM * 64 + g) * ASTR + kt * 8 + tig;
#pragma unroll
            for (int mt = 0; mt < 4; mt++) {
                const float* p = ab + mt * 16 * ASTR;
                af[mt][0] = __float_as_uint(p[0]);
                af[mt][1] = __float_as_uint(p[8 * ASTR]);
                af[mt][2] = __float_as_uint(p[4]);
                af[mt][3] = __float_as_uint(p[8 * ASTR + 4]);
            }
            const float* bb = Bs + (kt * 8 + tig) * BSTR + warpN * 32 + g;
#pragma unroll
            for (int nt = 0; nt < 4; nt++) {
                const float* p = bb + nt * 8;
                bf[nt][0] = __float_as_uint(p[0]);
                bf[nt][1] = __float_as_uint(p[4 * BSTR]);
            }
#pragma unroll
            for (int mt = 0; mt < 4; mt++)
#pragma unroll
                for (int nt = 0; nt < 4; nt++)
                    mma8(acc[mt][nt], af[mt], bf[nt]);
        }
        __syncthreads();
        if (c + 1 < NC) {
            sts((c + 1) & 1);
            __syncthreads();
        }
    }

    // epilogue
#pragma unroll
    for (int mt = 0; mt < 4; mt++) {
        const int row0 = m0 + warpM * 64 + mt * 16 + g;
        const int row1 = row0 + 8;
#pragma unroll
        for (int nt = 0; nt < 4; nt++) {
            const int col = n0 + warpN * 32 + nt * 8 + 2 * tig;
            float2 bz = make_float2(0.f, 0.f);
            if (BIAS) bz = *(const float2*)(bias + col);
            const float* cc = acc[mt][nt];
            if (row0 < NN)
                *(float2*)(outH + (size_t)row0 * N_TOT + col) =
                    make_float2(cc[0] + bz.x, cc[1] + bz.y);
            if (row1 < NN)
                *(float2*)(outH + (size_t)row1 * N_TOT + col) =
                    make_float2(cc[2] + bz.x, cc[3] + bz.y);
        }
    }
}

// ---------------------------------------------------------------- launch
extern "C" void kernel_launch(void* const* d_in, const int* in_sizes, int n_in,
                              void* d_out, int out_size) {
    const float* x    = (const float*)d_in[0];
    const int*   eidx = (const int*)d_in[1];
    const int*   midx = (const int*)d_in[2];
    const float* mtok = (const float*)d_in[3];
    const float* encW = (const float*)d_in[4];
    const float* encb = (const float*)d_in[5];
    const float* decW = (const float*)d_in[6];
    const float* decb = (const float*)d_in[7];
    const float* mlpW = (const float*)d_in[8];
    const float* mlpb = (const float*)d_in[9];

    const int nm = in_sizes[2];
    const int* src = eidx;
    const int* dst = eidx + EE;

    float *bufA, *bufB, *bufC;
    cudaGetSymbolAddress((void**)&bufA, g_bufA);
    cudaGetSymbolAddress((void**)&bufB, g_bufB);
    cudaGetSymbolAddress((void**)&bufC, g_bufC);
    float* out = (float*)d_out;

    const int SMEM = (2 * 128 * 36 + 2 * 32 * 132) * 4;   // 70656 B
    cudaFuncSetAttribute(k_mma<OUTC, INC,  true,  false, false>,
                         cudaFuncAttributeMaxDynamicSharedMemorySize, SMEM);
    cudaFuncSetAttribute(k_mma<OUTC, OUTC, false, false, false>,
                         cudaFuncAttributeMaxDynamicSharedMemorySize, SMEM);
    cudaFuncSetAttribute(k_mma<INC,  DECD, false, true,  true>,
                         cudaFuncAttributeMaxDynamicSharedMemorySize, SMEM);

    // CSR build + norm + mask flags
    k_zero<<<SBLK, 256>>>();
    k_deg<<<(EE + 255) / 256, 256>>>(dst);
    k_scan1<<<SBLK, 256>>>();
    k_scan2<<<1, 256>>>();
    k_scan3<<<SBLK, 256>>>();
    k_dinv<<<SBLK, 256>>>();
    k_fill<<<(EE + 255) / 256, 256>>>(src, dst);
    k_flag<<<(nm + 255) / 256, 256>>>(midx, nm);

    const int gatherBlocks = (NN + 3) / 4;

    // encoder: h1 = x_masked @ encW ; z = gather(h1) + self + encb
    k_mma<OUTC, INC, true, false, false><<<dim3(OUTC / 128, NBLK), 256, SMEM>>>(
        x, encW, bufA, nullptr, mtok);
    k_gather<<<gatherBlocks, 256>>>(bufA, encb, bufB);

    // decoder conv: h2pre = z @ decW ; h2 = gather(h2pre) + self + decb
    k_mma<OUTC, OUTC, false, false, false><<<dim3(OUTC / 128, NBLK), 256, SMEM>>>(
        bufB, decW, bufA, nullptr, nullptr);
    k_gather<<<gatherBlocks, 256>>>(bufA, decb, bufC);

    // mlp: x_recon = relu(h2) @ mlpW + mlpb
    k_mma<INC, DECD, false, true, true><<<dim3(INC / 128, NBLK), 256, SMEM>>>(
        bufC, mlpW, out, mlpb, nullptr);

    // output tail: x (slot 1), mask_indices as float (slot 2)
    const size_t reconElems = (size_t)NN * INC;
    k_copy_x<<<(int)((reconElems / 4 + 255) / 256), 256>>>(x, out + reconElems);
    k_midx_out<<<(nm + 255) / 256, 256>>>(midx, out + 2 * reconElems, nm);
}

// round 8
// speedup vs baseline: 2.6234x; 1.2395x over previous
#include <cuda_runtime.h>
#include <cuda_fp16.h>
#include <cstdint>
#include <cstddef>

#define NN   50000
#define EE   800000
#define INC  512
#define OUTC 256
#define DECD 256
#define NBLK 391        // ceil(NN/128)
#define SBLK 196        // ceil(NN/256)

// Scratch (device globals — no allocation allowed)
__device__ float g_dinv[NN];
__device__ int   g_flag[NN];
__device__ int   g_cnt[NN];
__device__ int   g_rowptr[NN + 1];
__device__ int   g_bsum[256];
__device__ int   g_cur[NN];
__device__ int   g_esrc[EE];
__device__ float g_bufA[(size_t)NN * OUTC];
__device__ float g_bufB[(size_t)NN * OUTC];
__device__ float g_bufC[(size_t)NN * OUTC];

// ---------------------------------------------------------------- CSR build
__global__ void k_zero() {
    int i = blockIdx.x * blockDim.x + threadIdx.x;
    if (i < NN) { g_cnt[i] = 0; g_flag[i] = 0; }
}
__global__ void k_deg(const int* __restrict__ dst) {
    int e = blockIdx.x * blockDim.x + threadIdx.x;
    if (e < EE) atomicAdd(&g_cnt[dst[e]], 1);
}
__global__ void k_scan1() {
    __shared__ int s[256];
    int gid = blockIdx.x * 256 + threadIdx.x;
    int v = (gid < NN) ? g_cnt[gid] : 0;
    s[threadIdx.x] = v;
    __syncthreads();
#pragma unroll
    for (int off = 1; off < 256; off <<= 1) {
        int t = (threadIdx.x >= off) ? s[threadIdx.x - off] : 0;
        __syncthreads();
        s[threadIdx.x] += t;
        __syncthreads();
    }
    if (gid < NN) g_rowptr[gid] = s[threadIdx.x] - v;     // block-local exclusive
    if (threadIdx.x == 255) g_bsum[blockIdx.x] = s[255];
}
__global__ void k_scan2() {
    __shared__ int s[256];
    int v = (threadIdx.x < SBLK) ? g_bsum[threadIdx.x] : 0;
    s[threadIdx.x] = v;
    __syncthreads();
#pragma unroll
    for (int off = 1; off < 256; off <<= 1) {
        int t = (threadIdx.x >= off) ? s[threadIdx.x - off] : 0;
        __syncthreads();
        s[threadIdx.x] += t;
        __syncthreads();
    }
    if (threadIdx.x < SBLK) g_bsum[threadIdx.x] = s[threadIdx.x] - v;  // exclusive
    if (threadIdx.x == 0) g_rowptr[NN] = EE;
}
__global__ void k_scan3() {     // global rowptr + cur + dinv (deg = cnt)
    int gid = blockIdx.x * 256 + threadIdx.x;
    if (gid < NN) {
        int r = g_rowptr[gid] + g_bsum[blockIdx.x];
        g_rowptr[gid] = r;
        g_cur[gid] = r;
        g_dinv[gid] = rsqrtf((float)g_cnt[gid] + 1.0f);
    }
}
__global__ void k_fill(const int* __restrict__ src, const int* __restrict__ dst) {
    int e = blockIdx.x * blockDim.x + threadIdx.x;
    if (e < EE) {
        int p = atomicAdd(&g_cur[dst[e]], 1);
        g_esrc[p] = src[e];
    }
}
__global__ void k_flag(const int* __restrict__ midx, int nm) {
    int i = blockIdx.x * blockDim.x + threadIdx.x;
    if (i < nm) g_flag[midx[i]] = 1;
}

// ---------------------------------------------------------------- output tail
__global__ void k_midx_out(const int* __restrict__ midx, float* __restrict__ out, int nm) {
    int i = blockIdx.x * blockDim.x + threadIdx.x;
    if (i < nm) out[i] = (float)midx[i];
}
__global__ void k_copy_x(const float* __restrict__ x, float* __restrict__ out) {
    size_t idx = (size_t)blockIdx.x * blockDim.x + threadIdx.x;
    if (idx < (size_t)NN * (INC / 4))
        *(float4*)(out + idx * 4) = *(const float4*)(x + idx * 4);
}

// ---------------------------------------------------------------- pull-mode aggregation
// z[node] = sum_{e: dst=node} h[src_e]*dinv[src_e]*dinv[node] + h[node]*dinv^2 + bias
__global__ void __launch_bounds__(256)
k_gather(const float* __restrict__ h, const float* __restrict__ bias,
         float* __restrict__ z) {
    const int node = blockIdx.x * 4 + (threadIdx.x >> 6);
    const int lane = threadIdx.x & 63;
    if (node >= NN) return;
    const int beg = g_rowptr[node];
    const int end = g_rowptr[node + 1];
    const float dn = g_dinv[node];

    const float4 bz = *(const float4*)(bias + lane * 4);
    float4 hv = *(const float4*)(h + (size_t)node * OUTC + lane * 4);
    const float s = dn * dn;
    float4 acc;
    acc.x = hv.x * s + bz.x;  acc.y = hv.y * s + bz.y;
    acc.z = hv.z * s + bz.z;  acc.w = hv.w * s + bz.w;

    int sidx = (beg < end) ? __ldg(&g_esrc[beg]) : 0;
    for (int i = beg; i < end; i++) {
        int nsidx = (i + 1 < end) ? __ldg(&g_esrc[i + 1]) : 0;
        float c = g_dinv[sidx] * dn;
        float4 v = *(const float4*)(h + (size_t)sidx * OUTC + lane * 4);
        acc.x += v.x * c;  acc.y += v.y * c;
        acc.z += v.z * c;  acc.w += v.w * c;
        sidx = nsidx;
    }
    *(float4*)(z + (size_t)node * OUTC + lane * 4) = acc;
}

// ---------------------------------------------------------------- fp16 mma.sync GEMM
__device__ __forceinline__ void mma16(float* c, const uint32_t* a, const uint32_t* b) {
    asm volatile(
        "mma.sync.aligned.m16n8k16.row.col.f32.f16.f16.f32 "
        "{%0,%1,%2,%3}, {%4,%5,%6,%7}, {%8,%9}, {%0,%1,%2,%3};"
        : "+f"(c[0]), "+f"(c[1]), "+f"(c[2]), "+f"(c[3])
        : "r"(a[0]), "r"(a[1]), "r"(a[2]), "r"(a[3]), "r"(b[0]), "r"(b[1]));
}
__device__ __forceinline__ uint2 pack4h(const float4& v) {
    __half2 h0 = __floats2half2_rn(v.x, v.y);
    __half2 h1 = __floats2half2_rn(v.z, v.w);
    uint2 r;
    r.x = *(const uint32_t*)&h0;
    r.y = *(const uint32_t*)&h1;
    return r;
}

// C[128-tile, 128-tile] = op(A[M,K_TOT]) @ W[K_TOT,N_TOT] (+ bias if BIAS)
// MASK: mask_token row substitution; RELU: relu at A load
template<int N_TOT, int K_TOT, bool MASK, bool RELU, bool BIAS>
__global__ void __launch_bounds__(256, 1)
k_mma(const float* __restrict__ A, const float* __restrict__ W,
      float* __restrict__ outH, const float* __restrict__ bias,
      const float* __restrict__ mtok)
{
    constexpr int NC   = K_TOT / 32;
    constexpr int ASTR = 40;               // halves per A row (32 + 8 pad)
    constexpr int BSTR = 136;              // halves per B row (128 + 8 pad)
    constexpr int ASZ  = 128 * ASTR;       // halves
    constexpr int BSZ  = 32 * BSTR;

    extern __shared__ __half sm[];
    __half* Abuf = sm;                     // 2 * ASZ
    __half* Bbuf = sm + 2 * ASZ;           // 2 * BSZ

    const int tid   = threadIdx.x;
    const int wid   = tid >> 5;
    const int lane  = tid & 31;
    const int g     = lane >> 2;
    const int tig   = lane & 3;
    const int warpM = wid >> 2;            // 0..1 -> 64 rows
    const int warpN = wid & 3;             // 0..3 -> 32 cols
    const int m0    = blockIdx.y * 128;
    const int n0    = blockIdx.x * 128;

    float acc[4][4][4];
#pragma unroll
    for (int mt = 0; mt < 4; mt++)
#pragma unroll
        for (int nt = 0; nt < 4; nt++)
#pragma unroll
            for (int i = 0; i < 4; i++) acc[mt][nt][i] = 0.0f;

    uint2 rA[4], rB[4];

    auto ldg = [&](int c) {
        const int k0 = c * 32;
#pragma unroll
        for (int t = 0; t < 4; t++) {
            int idx = tid + t * 256;
            int r = idx >> 3, q = idx & 7;
            int gr = m0 + r;
            float4 v = make_float4(0.f, 0.f, 0.f, 0.f);
            if (gr < NN) {
                const float* p;
                if (MASK && g_flag[gr]) p = mtok + k0 + q * 4;
                else                    p = A + (size_t)gr * K_TOT + k0 + q * 4;
                v = *(const float4*)p;
                if (RELU) {
                    v.x = fmaxf(v.x, 0.f); v.y = fmaxf(v.y, 0.f);
                    v.z = fmaxf(v.z, 0.f); v.w = fmaxf(v.w, 0.f);
                }
            }
            rA[t] = pack4h(v);
        }
#pragma unroll
        for (int t = 0; t < 4; t++) {
            int idx = tid + t * 256;
            int kk = idx >> 5, n4 = idx & 31;
            float4 v = *(const float4*)(W + (size_t)(k0 + kk) * N_TOT + n0 + n4 * 4);
            rB[t] = pack4h(v);
        }
    };
    auto sts = [&](int b) {
        __half* As = Abuf + b * ASZ;
        __half* Bs = Bbuf + b * BSZ;
#pragma unroll
        for (int t = 0; t < 4; t++) {
            int idx = tid + t * 256;
            int r = idx >> 3, q = idx & 7;
            *(uint2*)(As + r * ASTR + q * 4) = rA[t];
        }
#pragma unroll
        for (int t = 0; t < 4; t++) {
            int idx = tid + t * 256;
            int kk = idx >> 5, n4 = idx & 31;
            *(uint2*)(Bs + kk * BSTR + n4 * 4) = rB[t];
        }
    };

    ldg(0);
    sts(0);
    __syncthreads();

    for (int c = 0; c < NC; c++) {
        const int b = c & 1;
        if (c + 1 < NC) ldg(c + 1);        // overlap global loads with compute

        const __half* As = Abuf + b * ASZ;
        const __half* Bs = Bbuf + b * BSZ;
#pragma unroll
        for (int kt = 0; kt < 2; kt++) {
            uint32_t af[4][4], bf[4][2];
            const __half* ab = As + (warpM * 64 + g) * ASTR + kt * 16 + 2 * tig;
#pragma unroll
            for (int mt = 0; mt < 4; mt++) {
                const __half* p = ab + mt * 16 * ASTR;
                af[mt][0] = *(const uint32_t*)(p);
                af[mt][1] = *(const uint32_t*)(p + 8 * ASTR);
                af[mt][2] = *(const uint32_t*)(p + 8);
                af[mt][3] = *(const uint32_t*)(p + 8 * ASTR + 8);
            }
            const __half* bb = Bs + (kt * 16 + 2 * tig) * BSTR + warpN * 32 + g;
#pragma unroll
            for (int nt = 0; nt < 4; nt++) {
                const __half* p = bb + nt * 8;
                uint32_t lo0 = *(const uint16_t*)(p);
                uint32_t hi0 = *(const uint16_t*)(p + BSTR);
                uint32_t lo1 = *(const uint16_t*)(p + 8 * BSTR);
                uint32_t hi1 = *(const uint16_t*)(p + 9 * BSTR);
                bf[nt][0] = lo0 | (hi0 << 16);
                bf[nt][1] = lo1 | (hi1 << 16);
            }
#pragma unroll
            for (int mt = 0; mt < 4; mt++)
#pragma unroll
                for (int nt = 0; nt < 4; nt++)
                    mma16(acc[mt][nt], af[mt], bf[nt]);
        }
        __syncthreads();
        if (c + 1 < NC) {
            sts((c + 1) & 1);
            __syncthreads();
        }
    }

    // epilogue (m16n8k16 C layout == m16n8k8: c0,c1 row g; c2,c3 row g+8)
#pragma unroll
    for (int mt = 0; mt < 4; mt++) {
        const int row0 = m0 + warpM * 64 + mt * 16 + g;
        const int row1 = row0 + 8;
#pragma unroll
        for (int nt = 0; nt < 4; nt++) {
            const int col = n0 + warpN * 32 + nt * 8 + 2 * tig;
            float2 bz = make_float2(0.f, 0.f);
            if (BIAS) bz = *(const float2*)(bias + col);
            const float* cc = acc[mt][nt];
            if (row0 < NN)
                *(float2*)(outH + (size_t)row0 * N_TOT + col) =
                    make_float2(cc[0] + bz.x, cc[1] + bz.y);
            if (row1 < NN)
                *(float2*)(outH + (size_t)row1 * N_TOT + col) =
                    make_float2(cc[2] + bz.x, cc[3] + bz.y);
        }
    }
}

// ---------------------------------------------------------------- launch
extern "C" void kernel_launch(void* const* d_in, const int* in_sizes, int n_in,
                              void* d_out, int out_size) {
    const float* x    = (const float*)d_in[0];
    const int*   eidx = (const int*)d_in[1];
    const int*   midx = (const int*)d_in[2];
    const float* mtok = (const float*)d_in[3];
    const float* encW = (const float*)d_in[4];
    const float* encb = (const float*)d_in[5];
    const float* decW = (const float*)d_in[6];
    const float* decb = (const float*)d_in[7];
    const float* mlpW = (const float*)d_in[8];
    const float* mlpb = (const float*)d_in[9];

    const int nm = in_sizes[2];
    const int* src = eidx;
    const int* dst = eidx + EE;

    float *bufA, *bufB, *bufC;
    cudaGetSymbolAddress((void**)&bufA, g_bufA);
    cudaGetSymbolAddress((void**)&bufB, g_bufB);
    cudaGetSymbolAddress((void**)&bufC, g_bufC);
    float* out = (float*)d_out;

    const int SMEM = (2 * 128 * 40 + 2 * 32 * 136) * 2;   // 37888 B

    // CSR build + norm + mask flags
    k_zero<<<SBLK, 256>>>();
    k_deg<<<(EE + 255) / 256, 256>>>(dst);
    k_scan1<<<SBLK, 256>>>();
    k_scan2<<<1, 256>>>();
    k_scan3<<<SBLK, 256>>>();
    k_fill<<<(EE + 255) / 256, 256>>>(src, dst);
    k_flag<<<(nm + 255) / 256, 256>>>(midx, nm);

    const int gatherBlocks = (NN + 3) / 4;

    // encoder: h1 = x_masked @ encW ; z = gather(h1) + self + encb
    k_mma<OUTC, INC, true, false, false><<<dim3(OUTC / 128, NBLK), 256, SMEM>>>(
        x, encW, bufA, nullptr, mtok);
    k_gather<<<gatherBlocks, 256>>>(bufA, encb, bufB);

    // decoder conv: h2pre = z @ decW ; h2 = gather(h2pre) + self + decb
    k_mma<OUTC, OUTC, false, false, false><<<dim3(OUTC / 128, NBLK), 256, SMEM>>>(
        bufB, decW, bufA, nullptr, nullptr);
    k_gather<<<gatherBlocks, 256>>>(bufA, decb, bufC);

    // mlp: x_recon = relu(h2) @ mlpW + mlpb
    k_mma<INC, DECD, false, true, true><<<dim3(INC / 128, NBLK), 256, SMEM>>>(
        bufC, mlpW, out, mlpb, nullptr);

    // output tail: x (slot 1), mask_indices as float (slot 2)
    const size_t reconElems = (size_t)NN * INC;
    k_copy_x<<<(int)((reconElems / 4 + 255) / 256), 256>>>(x, out + reconElems);
    k_midx_out<<<(nm + 255) / 256, 256>>>(midx, out + 2 * reconElems, nm);
}

// round 9
// speedup vs baseline: 3.6568x; 1.3939x over previous
#include <cuda_runtime.h>
#include <cuda_fp16.h>
#include <cstdint>
#include <cstddef>

#define NN   50000
#define EE   800000
#define INC  512
#define OUTC 256
#define DECD 256
#define NBLK 391        // ceil(NN/128)
#define SBLK 196        // ceil(NN/256)

// Scratch (device globals — no allocation allowed)
__device__ float  g_dinv[NN];
__device__ int    g_flag[NN];
__device__ int    g_cnt[NN];
__device__ int    g_rowptr[NN + 1];
__device__ int    g_bsum[256];
__device__ int    g_cur[NN];
__device__ int    g_esrc[EE];
__device__ __half g_bufA[(size_t)NN * OUTC];
__device__ __half g_bufB[(size_t)NN * OUTC];
__device__ __half g_bufC[(size_t)NN * OUTC];

// ---------------------------------------------------------------- CSR build
__global__ void k_zero() {
    int i = blockIdx.x * blockDim.x + threadIdx.x;
    if (i < NN) { g_cnt[i] = 0; g_flag[i] = 0; }
}
__global__ void k_deg(const int* __restrict__ dst) {
    int e = blockIdx.x * blockDim.x + threadIdx.x;
    if (e < EE) atomicAdd(&g_cnt[dst[e]], 1);
}
__global__ void k_scan1() {
    __shared__ int s[256];
    int gid = blockIdx.x * 256 + threadIdx.x;
    int v = (gid < NN) ? g_cnt[gid] : 0;
    s[threadIdx.x] = v;
    __syncthreads();
#pragma unroll
    for (int off = 1; off < 256; off <<= 1) {
        int t = (threadIdx.x >= off) ? s[threadIdx.x - off] : 0;
        __syncthreads();
        s[threadIdx.x] += t;
        __syncthreads();
    }
    if (gid < NN) g_rowptr[gid] = s[threadIdx.x] - v;
    if (threadIdx.x == 255) g_bsum[blockIdx.x] = s[255];
}
__global__ void k_scan2() {
    __shared__ int s[256];
    int v = (threadIdx.x < SBLK) ? g_bsum[threadIdx.x] : 0;
    s[threadIdx.x] = v;
    __syncthreads();
#pragma unroll
    for (int off = 1; off < 256; off <<= 1) {
        int t = (threadIdx.x >= off) ? s[threadIdx.x - off] : 0;
        __syncthreads();
        s[threadIdx.x] += t;
        __syncthreads();
    }
    if (threadIdx.x < SBLK) g_bsum[threadIdx.x] = s[threadIdx.x] - v;
    if (threadIdx.x == 0) g_rowptr[NN] = EE;
}
__global__ void k_scan3() {     // global rowptr + cur + dinv (deg = cnt)
    int gid = blockIdx.x * 256 + threadIdx.x;
    if (gid < NN) {
        int r = g_rowptr[gid] + g_bsum[blockIdx.x];
        g_rowptr[gid] = r;
        g_cur[gid] = r;
        g_dinv[gid] = rsqrtf((float)g_cnt[gid] + 1.0f);
    }
}
__global__ void k_fill(const int* __restrict__ src, const int* __restrict__ dst) {
    int e = blockIdx.x * blockDim.x + threadIdx.x;
    if (e < EE) {
        int p = atomicAdd(&g_cur[dst[e]], 1);
        g_esrc[p] = src[e];
    }
}
__global__ void k_flag(const int* __restrict__ midx, int nm) {
    int i = blockIdx.x * blockDim.x + threadIdx.x;
    if (i < nm) g_flag[midx[i]] = 1;
}

// ---------------------------------------------------------------- output tail
__global__ void k_midx_out(const int* __restrict__ midx, float* __restrict__ out, int nm) {
    int i = blockIdx.x * blockDim.x + threadIdx.x;
    if (i < nm) out[i] = (float)midx[i];
}
__global__ void k_copy_x(const float* __restrict__ x, float* __restrict__ out) {
    size_t idx = (size_t)blockIdx.x * blockDim.x + threadIdx.x;
    if (idx < (size_t)NN * (INC / 4))
        *(float4*)(out + idx * 4) = *(const float4*)(x + idx * 4);
}

// ---------------------------------------------------------------- pull-mode aggregation (half in/out, fp32 accum)
// z[node] = sum_{e: dst=node} h[src_e]*dinv[src]*dinv[node] + h[node]*dinv^2 + bias
__global__ void __launch_bounds__(256)
k_gather(const __half* __restrict__ h, const float* __restrict__ bias,
         __half* __restrict__ z) {
    const int node = blockIdx.x * 4 + (threadIdx.x >> 6);
    const int lane = threadIdx.x & 63;
    if (node >= NN) return;
    const int beg = g_rowptr[node];
    const int end = g_rowptr[node + 1];
    const float dn = g_dinv[node];

    const float4 bz = *(const float4*)(bias + lane * 4);
    uint2 hv = *(const uint2*)(h + (size_t)node * OUTC + lane * 4);
    float2 h0 = __half22float2(*(const __half2*)&hv.x);
    float2 h1 = __half22float2(*(const __half2*)&hv.y);
    const float s = dn * dn;
    float4 acc;
    acc.x = h0.x * s + bz.x;  acc.y = h0.y * s + bz.y;
    acc.z = h1.x * s + bz.z;  acc.w = h1.y * s + bz.w;

    int sidx = (beg < end) ? __ldg(&g_esrc[beg]) : 0;
    for (int i = beg; i < end; i++) {
        int nsidx = (i + 1 < end) ? __ldg(&g_esrc[i + 1]) : 0;
        float c = g_dinv[sidx] * dn;
        uint2 v = *(const uint2*)(h + (size_t)sidx * OUTC + lane * 4);
        float2 v0 = __half22float2(*(const __half2*)&v.x);
        float2 v1 = __half22float2(*(const __half2*)&v.y);
        acc.x += v0.x * c;  acc.y += v0.y * c;
        acc.z += v1.x * c;  acc.w += v1.y * c;
        sidx = nsidx;
    }
    uint2 st;
    *(__half2*)&st.x = __floats2half2_rn(acc.x, acc.y);
    *(__half2*)&st.y = __floats2half2_rn(acc.z, acc.w);
    *(uint2*)(z + (size_t)node * OUTC + lane * 4) = st;
}

// ---------------------------------------------------------------- fp16 mma.sync GEMM (ldmatrix)
__device__ __forceinline__ void mma16(float* c, const uint32_t* a, const uint32_t* b) {
    asm volatile(
        "mma.sync.aligned.m16n8k16.row.col.f32.f16.f16.f32 "
        "{%0,%1,%2,%3}, {%4,%5,%6,%7}, {%8,%9}, {%0,%1,%2,%3};"
        : "+f"(c[0]), "+f"(c[1]), "+f"(c[2]), "+f"(c[3])
        : "r"(a[0]), "r"(a[1]), "r"(a[2]), "r"(a[3]), "r"(b[0]), "r"(b[1]));
}
__device__ __forceinline__ void ldsm_x4(uint32_t* r, uint32_t sa) {
    asm volatile("ldmatrix.sync.aligned.m8n8.x4.shared.b16 {%0,%1,%2,%3}, [%4];"
                 : "=r"(r[0]), "=r"(r[1]), "=r"(r[2]), "=r"(r[3]) : "r"(sa));
}
__device__ __forceinline__ void ldsm_x4t(uint32_t* r, uint32_t sa) {
    asm volatile("ldmatrix.sync.aligned.m8n8.x4.trans.shared.b16 {%0,%1,%2,%3}, [%4];"
                 : "=r"(r[0]), "=r"(r[1]), "=r"(r[2]), "=r"(r[3]) : "r"(sa));
}
__device__ __forceinline__ uint2 pack4h(const float4& v) {
    __half2 h0 = __floats2half2_rn(v.x, v.y);
    __half2 h1 = __floats2half2_rn(v.z, v.w);
    uint2 r;
    r.x = *(const uint32_t*)&h0;
    r.y = *(const uint32_t*)&h1;
    return r;
}

// C[128-tile, 128-tile] = op(A[M,K_TOT]) @ W[K_TOT,N_TOT] (+ bias if OUTF32)
// INF32: A is float (else half). MASK: mask_token rows. RELU: relu at A load.
// OUTF32: write float + bias (else half, no bias).
template<int N_TOT, int K_TOT, bool INF32, bool MASK, bool RELU, bool OUTF32>
__global__ void __launch_bounds__(256)
k_mma(const void* __restrict__ Ain, const float* __restrict__ W,
      void* __restrict__ outp, const float* __restrict__ bias,
      const float* __restrict__ mtok)
{
    constexpr int NC   = K_TOT / 32;
    constexpr int ASTR = 40;               // halves per A smem row (32 + 8 pad)
    constexpr int BSTR = 136;              // halves per B smem row (128 + 8 pad)
    constexpr int ASZ  = 128 * ASTR;
    constexpr int BSZ  = 32 * BSTR;

    extern __shared__ __half sm[];
    __half* Abuf = sm;
    __half* Bbuf = sm + 2 * ASZ;

    const int tid   = threadIdx.x;
    const int wid   = tid >> 5;
    const int lane  = tid & 31;
    const int g     = lane >> 2;
    const int tig   = lane & 3;
    const int warpM = wid >> 2;            // 0..1 -> 64 rows
    const int warpN = wid & 3;             // 0..3 -> 32 cols
    const int m0    = blockIdx.y * 128;
    const int n0    = blockIdx.x * 128;

    float acc[4][4][4];
#pragma unroll
    for (int mt = 0; mt < 4; mt++)
#pragma unroll
        for (int nt = 0; nt < 4; nt++)
#pragma unroll
            for (int i = 0; i < 4; i++) acc[mt][nt][i] = 0.0f;

    uint2 rA[4], rB[4];

    auto ldg = [&](int c) {
        const int k0 = c * 32;
#pragma unroll
        for (int t = 0; t < 4; t++) {
            int idx = tid + t * 256;
            int r = idx >> 3, q = idx & 7;       // row, group of 4 elems
            int gr = m0 + r;
            if (INF32) {
                const float* A = (const float*)Ain;
                float4 v = make_float4(0.f, 0.f, 0.f, 0.f);
                if (gr < NN) {
                    const float* p;
                    if (MASK && g_flag[gr]) p = mtok + k0 + q * 4;
                    else                    p = A + (size_t)gr * K_TOT + k0 + q * 4;
                    v = *(const float4*)p;
                }
                rA[t] = pack4h(v);
            } else {
                const __half* A = (const __half*)Ain;
                uint2 v = make_uint2(0u, 0u);
                if (gr < NN)
                    v = *(const uint2*)(A + (size_t)gr * K_TOT + k0 + q * 4);
                if (RELU) {
                    const __half2 z2 = __float2half2_rn(0.f);
                    *(__half2*)&v.x = __hmax2(*(__half2*)&v.x, z2);
                    *(__half2*)&v.y = __hmax2(*(__half2*)&v.y, z2);
                }
                rA[t] = v;
            }
        }
#pragma unroll
        for (int t = 0; t < 4; t++) {
            int idx = tid + t * 256;
            int kk = idx >> 5, n4 = idx & 31;
            float4 v = *(const float4*)(W + (size_t)(k0 + kk) * N_TOT + n0 + n4 * 4);
            rB[t] = pack4h(v);
        }
    };
    auto sts = [&](int b) {
        __half* As = Abuf + b * ASZ;
        __half* Bs = Bbuf + b * BSZ;
#pragma unroll
        for (int t = 0; t < 4; t++) {
            int idx = tid + t * 256;
            int r = idx >> 3, q = idx & 7;
            *(uint2*)(As + r * ASTR + q * 4) = rA[t];
        }
#pragma unroll
        for (int t = 0; t < 4; t++) {
            int idx = tid + t * 256;
            int kk = idx >> 5, n4 = idx & 31;
            *(uint2*)(Bs + kk * BSTR + n4 * 4) = rB[t];
        }
    };

    // per-lane ldmatrix address components (byte offsets within buffers)
    const uint32_t aRow = (uint32_t)(warpM * 64 + (lane & 15));
    const uint32_t aOff = (aRow * ASTR + (uint32_t)((lane >> 4) * 8)) * 2;
    const uint32_t bKr  = (uint32_t)(((lane >> 3) & 1) * 8 + (lane & 7));
    const uint32_t bNc  = (uint32_t)(warpN * 32 + (lane >> 4) * 8);

    ldg(0);
    sts(0);
    __syncthreads();

    for (int c = 0; c < NC; c++) {
        const int b = c & 1;
        if (c + 1 < NC) ldg(c + 1);        // overlap global loads with compute

        const uint32_t Asb = (uint32_t)__cvta_generic_to_shared(Abuf + b * ASZ);
        const uint32_t Bsb = (uint32_t)__cvta_generic_to_shared(Bbuf + b * BSZ);
#pragma unroll
        for (int kt = 0; kt < 2; kt++) {
            uint32_t af[4][4], bf[4][2];
#pragma unroll
            for (int mt = 0; mt < 4; mt++)
                ldsm_x4(af[mt], Asb + aOff + (uint32_t)((mt * 16 * ASTR + kt * 16) * 2));
#pragma unroll
            for (int p = 0; p < 2; p++) {
                uint32_t r[4];
                ldsm_x4t(r, Bsb + (uint32_t)((((kt * 16 + bKr) * BSTR) + bNc + p * 16) * 2));
                bf[2 * p][0] = r[0];  bf[2 * p][1] = r[1];
                bf[2 * p + 1][0] = r[2];  bf[2 * p + 1][1] = r[3];
            }
#pragma unroll
            for (int mt = 0; mt < 4; mt++)
#pragma unroll
                for (int nt = 0; nt < 4; nt++)
                    mma16(acc[mt][nt], af[mt], bf[nt]);
        }
        __syncthreads();
        if (c + 1 < NC) {
            sts((c + 1) & 1);
            __syncthreads();
        }
    }

    // epilogue
#pragma unroll
    for (int mt = 0; mt < 4; mt++) {
        const int row0 = m0 + warpM * 64 + mt * 16 + g;
        const int row1 = row0 + 8;
#pragma unroll
        for (int nt = 0; nt < 4; nt++) {
            const int col = n0 + warpN * 32 + nt * 8 + 2 * tig;
            const float* cc = acc[mt][nt];
            if (OUTF32) {
                float* outF = (float*)outp;
                const float2 bz = *(const float2*)(bias + col);
                if (row0 < NN)
                    *(float2*)(outF + (size_t)row0 * N_TOT + col) =
                        make_float2(cc[0] + bz.x, cc[1] + bz.y);
                if (row1 < NN)
                    *(float2*)(outF + (size_t)row1 * N_TOT + col) =
                        make_float2(cc[2] + bz.x, cc[3] + bz.y);
            } else {
                __half* outH = (__half*)outp;
                if (row0 < NN) {
                    __half2 h = __floats2half2_rn(cc[0], cc[1]);
                    *(uint32_t*)(outH + (size_t)row0 * N_TOT + col) = *(const uint32_t*)&h;
                }
                if (row1 < NN) {
                    __half2 h = __floats2half2_rn(cc[2], cc[3]);
                    *(uint32_t*)(outH + (size_t)row1 * N_TOT + col) = *(const uint32_t*)&h;
                }
            }
        }
    }
}

// ---------------------------------------------------------------- launch
extern "C" void kernel_launch(void* const* d_in, const int* in_sizes, int n_in,
                              void* d_out, int out_size) {
    const float* x    = (const float*)d_in[0];
    const int*   eidx = (const int*)d_in[1];
    const int*   midx = (const int*)d_in[2];
    const float* mtok = (const float*)d_in[3];
    const float* encW = (const float*)d_in[4];
    const float* encb = (const float*)d_in[5];
    const float* decW = (const float*)d_in[6];
    const float* decb = (const float*)d_in[7];
    const float* mlpW = (const float*)d_in[8];
    const float* mlpb = (const float*)d_in[9];

    const int nm = in_sizes[2];
    const int* src = eidx;
    const int* dst = eidx + EE;

    __half *bufA, *bufB, *bufC;
    cudaGetSymbolAddress((void**)&bufA, g_bufA);
    cudaGetSymbolAddress((void**)&bufB, g_bufB);
    cudaGetSymbolAddress((void**)&bufC, g_bufC);
    float* out = (float*)d_out;

    const int SMEM = (2 * 128 * 40 + 2 * 32 * 136) * 2;   // 37888 B

    // CSR build + norm + mask flags
    k_zero<<<SBLK, 256>>>();
    k_deg<<<(EE + 255) / 256, 256>>>(dst);
    k_scan1<<<SBLK, 256>>>();
    k_scan2<<<1, 256>>>();
    k_scan3<<<SBLK, 256>>>();
    k_fill<<<(EE + 255) / 256, 256>>>(src, dst);
    k_flag<<<(nm + 255) / 256, 256>>>(midx, nm);

    const int gatherBlocks = (NN + 3) / 4;

    // encoder: h1 = x_masked @ encW ; z = gather(h1) + self + encb
    k_mma<OUTC, INC, true, true, false, false><<<dim3(OUTC / 128, NBLK), 256, SMEM>>>(
        x, encW, bufA, nullptr, mtok);
    k_gather<<<gatherBlocks, 256>>>(bufA, encb, bufB);

    // decoder conv: h2pre = z @ decW ; h2 = gather(h2pre) + self + decb
    k_mma<OUTC, OUTC, false, false, false, false><<<dim3(OUTC / 128, NBLK), 256, SMEM>>>(
        bufB, decW, bufA, nullptr, nullptr);
    k_gather<<<gatherBlocks, 256>>>(bufA, decb, bufC);

    // mlp: x_recon = relu(h2) @ mlpW + mlpb
    k_mma<INC, DECD, false, false, true, true><<<dim3(INC / 128, NBLK), 256, SMEM>>>(
        bufC, mlpW, out, mlpb, nullptr);

    // output tail: x (slot 1), mask_indices as float (slot 2)
    const size_t reconElems = (size_t)NN * INC;
    k_copy_x<<<(int)((reconElems / 4 + 255) / 256), 256>>>(x, out + reconElems);
    k_midx_out<<<(nm + 255) / 256, 256>>>(midx, out + 2 * reconElems, nm);
}

// round 14
// speedup vs baseline: 4.0436x; 1.1058x over previous
#include <cuda_runtime.h>
#include <cuda_fp16.h>
#include <cstdint>
#include <cstddef>

#define NN   50000
#define EE   800000
#define INC  512
#define OUTC 256
#define DECD 256
#define NBLK 391        // ceil(NN/128)
#define SBLK 196        // ceil(NN/256)

// Scratch (device globals — no allocation allowed)
__device__ float  g_dinv[NN];
__device__ int    g_flag[NN];
__device__ int    g_cnt[NN];
__device__ int    g_rowptr[NN + 1];
__device__ int    g_bsum[256];
__device__ int    g_cur[NN];
__device__ int    g_esrc[EE];
__device__ __half g_bufA[(size_t)NN * OUTC];
__device__ __half g_bufB[(size_t)NN * OUTC];
__device__ __half g_bufC[(size_t)NN * OUTC];

// ---------------------------------------------------------------- CSR build
__global__ void k_zero() {
    int i = blockIdx.x * blockDim.x + threadIdx.x;
    if (i < NN) g_cnt[i] = 0;
}
__global__ void k_deg(const int* __restrict__ dst) {
    int e = blockIdx.x * blockDim.x + threadIdx.x;
    if (e < EE) atomicAdd(&g_cnt[dst[e]], 1);
}
__global__ void k_scan1() {
    __shared__ int s[256];
    int gid = blockIdx.x * 256 + threadIdx.x;
    int v = (gid < NN) ? g_cnt[gid] : 0;
    s[threadIdx.x] = v;
    __syncthreads();
#pragma unroll
    for (int off = 1; off < 256; off <<= 1) {
        int t = (threadIdx.x >= off) ? s[threadIdx.x - off] : 0;
        __syncthreads();
        s[threadIdx.x] += t;
        __syncthreads();
    }
    if (gid < NN) g_rowptr[gid] = s[threadIdx.x] - v;
    if (threadIdx.x == 255) g_bsum[blockIdx.x] = s[255];
}
__global__ void k_scan2() {
    __shared__ int s[256];
    int v = (threadIdx.x < SBLK) ? g_bsum[threadIdx.x] : 0;
    s[threadIdx.x] = v;
    __syncthreads();
#pragma unroll
    for (int off = 1; off < 256; off <<= 1) {
        int t = (threadIdx.x >= off) ? s[threadIdx.x - off] : 0;
        __syncthreads();
        s[threadIdx.x] += t;
        __syncthreads();
    }
    if (threadIdx.x < SBLK) g_bsum[threadIdx.x] = s[threadIdx.x] - v;
    if (threadIdx.x == 0) g_rowptr[NN] = EE;
}
__global__ void k_scan3() {     // global rowptr + cur + dinv (deg = cnt)
    int gid = blockIdx.x * 256 + threadIdx.x;
    if (gid < NN) {
        int r = g_rowptr[gid] + g_bsum[blockIdx.x];
        g_rowptr[gid] = r;
        g_cur[gid] = r;
        g_dinv[gid] = rsqrtf((float)g_cnt[gid] + 1.0f);
    }
}
__global__ void k_fill(const int* __restrict__ src, const int* __restrict__ dst) {
    int e = blockIdx.x * blockDim.x + threadIdx.x;
    if (e < EE) {
        int p = atomicAdd(&g_cur[dst[e]], 1);
        g_esrc[p] = src[e];
    }
}
__global__ void k_zeroflag() {
    int i = blockIdx.x * blockDim.x + threadIdx.x;
    if (i < NN) g_flag[i] = 0;
}
__global__ void k_flag(const int* __restrict__ midx, int nm) {
    int i = blockIdx.x * blockDim.x + threadIdx.x;
    if (i < nm) g_flag[midx[i]] = 1;
}

// ---------------------------------------------------------------- output tail (x copy + midx convert)
__global__ void k_tail(const float* __restrict__ x, const int* __restrict__ midx,
                       float* __restrict__ out, int nm) {
    const int NX = NN * (INC / 4);
    int i = blockIdx.x * 256 + threadIdx.x;
    if (i < NX)
        *(float4*)(out + (size_t)NN * INC + (size_t)i * 4) = ((const float4*)x)[i];
    int j = i - NX;
    if (j >= 0 && j < nm)
        out[2 * (size_t)NN * INC + j] = (float)midx[j];
}

// ---------------------------------------------------------------- pull-mode aggregation (half in/out, fp32 accum)
__global__ void __launch_bounds__(256)
k_gather(const __half* __restrict__ h, const float* __restrict__ bias,
         __half* __restrict__ z) {
    const int node = blockIdx.x * 4 + (threadIdx.x >> 6);
    const int lane = threadIdx.x & 63;
    if (node >= NN) return;
    const int beg = g_rowptr[node];
    const int end = g_rowptr[node + 1];
    const float dn = g_dinv[node];

    const float4 bz = *(const float4*)(bias + lane * 4);
    uint2 hv = *(const uint2*)(h + (size_t)node * OUTC + lane * 4);
    float2 h0 = __half22float2(*(const __half2*)&hv.x);
    float2 h1 = __half22float2(*(const __half2*)&hv.y);
    const float s = dn * dn;
    float4 acc;
    acc.x = h0.x * s + bz.x;  acc.y = h0.y * s + bz.y;
    acc.z = h1.x * s + bz.z;  acc.w = h1.y * s + bz.w;

    int sidx = (beg < end) ? __ldg(&g_esrc[beg]) : 0;
    for (int i = beg; i < end; i++) {
        int nsidx = (i + 1 < end) ? __ldg(&g_esrc[i + 1]) : 0;
        float c = g_dinv[sidx] * dn;
        uint2 v = *(const uint2*)(h + (size_t)sidx * OUTC + lane * 4);
        float2 v0 = __half22float2(*(const __half2*)&v.x);
        float2 v1 = __half22float2(*(const __half2*)&v.y);
        acc.x += v0.x * c;  acc.y += v0.y * c;
        acc.z += v1.x * c;  acc.w += v1.y * c;
        sidx = nsidx;
    }
    uint2 st;
    *(__half2*)&st.x = __floats2half2_rn(acc.x, acc.y);
    *(__half2*)&st.y = __floats2half2_rn(acc.z, acc.w);
    *(uint2*)(z + (size_t)node * OUTC + lane * 4) = st;
}

// ---------------------------------------------------------------- fp16 mma.sync GEMM (ldmatrix, single-sync pipeline)
__device__ __forceinline__ void mma16(float* c, const uint32_t* a, const uint32_t* b) {
    asm volatile(
        "mma.sync.aligned.m16n8k16.row.col.f32.f16.f16.f32 "
        "{%0,%1,%2,%3}, {%4,%5,%6,%7}, {%8,%9}, {%0,%1,%2,%3};"
        : "+f"(c[0]), "+f"(c[1]), "+f"(c[2]), "+f"(c[3])
        : "r"(a[0]), "r"(a[1]), "r"(a[2]), "r"(a[3]), "r"(b[0]), "r"(b[1]));
}
__device__ __forceinline__ void ldsm_x4(uint32_t* r, uint32_t sa) {
    asm volatile("ldmatrix.sync.aligned.m8n8.x4.shared.b16 {%0,%1,%2,%3}, [%4];"
                 : "=r"(r[0]), "=r"(r[1]), "=r"(r[2]), "=r"(r[3]) : "r"(sa));
}
__device__ __forceinline__ void ldsm_x4t(uint32_t* r, uint32_t sa) {
    asm volatile("ldmatrix.sync.aligned.m8n8.x4.trans.shared.b16 {%0,%1,%2,%3}, [%4];"
                 : "=r"(r[0]), "=r"(r[1]), "=r"(r[2]), "=r"(r[3]) : "r"(sa));
}
__device__ __forceinline__ uint2 pack4h(const float4& v) {
    __half2 h0 = __floats2half2_rn(v.x, v.y);
    __half2 h1 = __floats2half2_rn(v.z, v.w);
    uint2 r;
    r.x = *(const uint32_t*)&h0;
    r.y = *(const uint32_t*)&h1;
    return r;
}

template<int N_TOT, int K_TOT, bool INF32, bool MASK, bool RELU, bool OUTF32>
__global__ void __launch_bounds__(256)
k_mma(const void* __restrict__ Ain, const float* __restrict__ W,
      void* __restrict__ outp, const float* __restrict__ bias,
      const float* __restrict__ mtok)
{
    constexpr int NC   = K_TOT / 32;
    constexpr int ASTR = 40;
    constexpr int BSTR = 136;
    constexpr int ASZ  = 128 * ASTR;
    constexpr int BSZ  = 32 * BSTR;

    extern __shared__ __half sm[];
    __half* Abuf = sm;
    __half* Bbuf = sm + 2 * ASZ;

    const int tid   = threadIdx.x;
    const int wid   = tid >> 5;
    const int lane  = tid & 31;
    const int g     = lane >> 2;
    const int tig   = lane & 3;
    const int warpM = wid >> 2;
    const int warpN = wid & 3;
    const int m0    = blockIdx.y * 128;
    const int n0    = blockIdx.x * 128;

    float acc[4][4][4];
#pragma unroll
    for (int mt = 0; mt < 4; mt++)
#pragma unroll
        for (int nt = 0; nt < 4; nt++)
#pragma unroll
            for (int i = 0; i < 4; i++) acc[mt][nt][i] = 0.0f;

    uint2 rA[4], rB[4];

    auto ldg = [&](int c) {
        const int k0 = c * 32;
#pragma unroll
        for (int t = 0; t < 4; t++) {
            int idx = tid + t * 256;
            int r = idx >> 3, q = idx & 7;
            int gr = m0 + r;
            if (INF32) {
                const float* A = (const float*)Ain;
                float4 v = make_float4(0.f, 0.f, 0.f, 0.f);
                if (gr < NN) {
                    const float* p;
                    if (MASK && g_flag[gr]) p = mtok + k0 + q * 4;
                    else                    p = A + (size_t)gr * K_TOT + k0 + q * 4;
                    v = *(const float4*)p;
                }
                rA[t] = pack4h(v);
            } else {
                const __half* A = (const __half*)Ain;
                uint2 v = make_uint2(0u, 0u);
                if (gr < NN)
                    v = *(const uint2*)(A + (size_t)gr * K_TOT + k0 + q * 4);
                if (RELU) {
                    const __half2 z2 = __float2half2_rn(0.f);
                    *(__half2*)&v.x = __hmax2(*(__half2*)&v.x, z2);
                    *(__half2*)&v.y = __hmax2(*(__half2*)&v.y, z2);
                }
                rA[t] = v;
            }
        }
#pragma unroll
        for (int t = 0; t < 4; t++) {
            int idx = tid + t * 256;
            int kk = idx >> 5, n4 = idx & 31;
            float4 v = *(const float4*)(W + (size_t)(k0 + kk) * N_TOT + n0 + n4 * 4);
            rB[t] = pack4h(v);
        }
    };
    auto sts = [&](int b) {
        __half* As = Abuf + b * ASZ;
        __half* Bs = Bbuf + b * BSZ;
#pragma unroll
        for (int t = 0; t < 4; t++) {
            int idx = tid + t * 256;
            int r = idx >> 3, q = idx & 7;
            *(uint2*)(As + r * ASTR + q * 4) = rA[t];
        }
#pragma unroll
        for (int t = 0; t < 4; t++) {
            int idx = tid + t * 256;
            int kk = idx >> 5, n4 = idx & 31;
            *(uint2*)(Bs + kk * BSTR + n4 * 4) = rB[t];
        }
    };

    const uint32_t aRow = (uint32_t)(warpM * 64 + (lane & 15));
    const uint32_t aOff = (aRow * ASTR + (uint32_t)((lane >> 4) * 8)) * 2;
    const uint32_t bKr  = (uint32_t)(((lane >> 3) & 1) * 8 + (lane & 7));
    const uint32_t bNc  = (uint32_t)(warpN * 32 + (lane >> 4) * 8);

    ldg(0);
    sts(0);
    __syncthreads();

    for (int c = 0; c < NC; c++) {
        const int b = c & 1;
        if (c + 1 < NC) ldg(c + 1);        // global loads in flight during mma

        const uint32_t Asb = (uint32_t)__cvta_generic_to_shared(Abuf + b * ASZ);
        const uint32_t Bsb = (uint32_t)__cvta_generic_to_shared(Bbuf + b * BSZ);
#pragma unroll
        for (int kt = 0; kt < 2; kt++) {
            uint32_t af[4][4], bf[4][2];
#pragma unroll
            for (int mt = 0; mt < 4; mt++)
                ldsm_x4(af[mt], Asb + aOff + (uint32_t)((mt * 16 * ASTR + kt * 16) * 2));
#pragma unroll
            for (int p = 0; p < 2; p++) {
                uint32_t r[4];
                ldsm_x4t(r, Bsb + (uint32_t)((((kt * 16 + bKr) * BSTR) + bNc + p * 16) * 2));
                bf[2 * p][0] = r[0];  bf[2 * p][1] = r[1];
                bf[2 * p + 1][0] = r[2];  bf[2 * p + 1][1] = r[3];
            }
#pragma unroll
            for (int mt = 0; mt < 4; mt++)
#pragma unroll
                for (int nt = 0; nt < 4; nt++)
                    mma16(acc[mt][nt], af[mt], bf[nt]);
        }
        // single barrier per chunk: write NEXT chunk into the buffer not read
        // this iteration (its last readers passed the previous barrier).
        if (c + 1 < NC) sts((c + 1) & 1);
        __syncthreads();
    }

    // epilogue
#pragma unroll
    for (int mt = 0; mt < 4; mt++) {
        const int row0 = m0 + warpM * 64 + mt * 16 + g;
        const int row1 = row0 + 8;
#pragma unroll
        for (int nt = 0; nt < 4; nt++) {
            const int col = n0 + warpN * 32 + nt * 8 + 2 * tig;
            const float* cc = acc[mt][nt];
            if (OUTF32) {
                float* outF = (float*)outp;
                const float2 bz = *(const float2*)(bias + col);
                if (row0 < NN)
                    *(float2*)(outF + (size_t)row0 * N_TOT + col) =
                        make_float2(cc[0] + bz.x, cc[1] + bz.y);
                if (row1 < NN)
                    *(float2*)(outF + (size_t)row1 * N_TOT + col) =
                        make_float2(cc[2] + bz.x, cc[3] + bz.y);
            } else {
                __half* outH = (__half*)outp;
                if (row0 < NN) {
                    __half2 h = __floats2half2_rn(cc[0], cc[1]);
                    *(uint32_t*)(outH + (size_t)row0 * N_TOT + col) = *(const uint32_t*)&h;
                }
                if (row1 < NN) {
                    __half2 h = __floats2half2_rn(cc[2], cc[3]);
                    *(uint32_t*)(outH + (size_t)row1 * N_TOT + col) = *(const uint32_t*)&h;
                }
            }
        }
    }
}

// ---------------------------------------------------------------- launch
extern "C" void kernel_launch(void* const* d_in, const int* in_sizes, int n_in,
                              void* d_out, int out_size) {
    const float* x    = (const float*)d_in[0];
    const int*   eidx = (const int*)d_in[1];
    const int*   midx = (const int*)d_in[2];
    const float* mtok = (const float*)d_in[3];
    const float* encW = (const float*)d_in[4];
    const float* encb = (const float*)d_in[5];
    const float* decW = (const float*)d_in[6];
    const float* decb = (const float*)d_in[7];
    const float* mlpW = (const float*)d_in[8];
    const float* mlpb = (const float*)d_in[9];

    const int nm = in_sizes[2];
    const int* src = eidx;
    const int* dst = eidx + EE;

    __half *bufA, *bufB, *bufC;
    cudaGetSymbolAddress((void**)&bufA, g_bufA);
    cudaGetSymbolAddress((void**)&bufB, g_bufB);
    cudaGetSymbolAddress((void**)&bufC, g_bufC);
    float* out = (float*)d_out;

    const int SMEM = (2 * 128 * 40 + 2 * 32 * 136) * 2;   // 37888 B

    // side streams + events (host objects, created once)
    static cudaStream_t sCsr = nullptr, sTail = nullptr;
    static cudaEvent_t  eFork = nullptr, eCsr = nullptr, eTail = nullptr;
    if (!sCsr) {
        cudaStreamCreateWithFlags(&sCsr, cudaStreamNonBlocking);
        cudaStreamCreateWithFlags(&sTail, cudaStreamNonBlocking);
        cudaEventCreateWithFlags(&eFork, cudaEventDisableTiming);
        cudaEventCreateWithFlags(&eCsr, cudaEventDisableTiming);
        cudaEventCreateWithFlags(&eTail, cudaEventDisableTiming);
    }

    // fork side streams from the capture stream
    cudaEventRecord(eFork, 0);
    cudaStreamWaitEvent(sCsr, eFork, 0);
    cudaStreamWaitEvent(sTail, eFork, 0);

    // --- sCsr: CSR build + dinv (needed only by gather1) ---
    k_zero<<<SBLK, 256, 0, sCsr>>>();
    k_deg<<<(EE + 255) / 256, 256, 0, sCsr>>>(dst);
    k_scan1<<<SBLK, 256, 0, sCsr>>>();
    k_scan2<<<1, 256, 0, sCsr>>>();
    k_scan3<<<SBLK, 256, 0, sCsr>>>();
    k_fill<<<(EE + 255) / 256, 256, 0, sCsr>>>(src, dst);
    cudaEventRecord(eCsr, sCsr);

    // --- sTail: output slots 1+2 (independent of everything) ---
    k_tail<<<(NN * (INC / 4) + nm + 255) / 256, 256, 0, sTail>>>(x, midx, out, nm);
    cudaEventRecord(eTail, sTail);

    // --- main stream: mask flags -> GEMM1 (overlaps CSR build) ---
    k_zeroflag<<<SBLK, 256>>>();
    k_flag<<<(nm + 255) / 256, 256>>>(midx, nm);
    k_mma<OUTC, INC, true, true, false, false><<<dim3(OUTC / 128, NBLK), 256, SMEM>>>(
        x, encW, bufA, nullptr, mtok);

    cudaStreamWaitEvent(0, eCsr, 0);      // join CSR before gather1

    const int gatherBlocks = (NN + 3) / 4;
    k_gather<<<gatherBlocks, 256>>>(bufA, encb, bufB);

    k_mma<OUTC, OUTC, false, false, false, false><<<dim3(OUTC / 128, NBLK), 256, SMEM>>>(
        bufB, decW, bufA, nullptr, nullptr);
    k_gather<<<gatherBlocks, 256>>>(bufA, decb, bufC);

    k_mma<INC, DECD, false, false, true, true><<<dim3(INC / 128, NBLK), 256, SMEM>>>(
        bufC, mlpW, out, mlpb, nullptr);

    cudaStreamWaitEvent(0, eTail, 0);     // join tail copy before returning
}